// round 5
// baseline (speedup 1.0000x reference)
#include <cuda_runtime.h>
#include <cstdint>

#define NP 1024
#define NUP 512
#define TWOPI_L 0.6283185307179586f
#define INVN (1.0f/1024.0f)

// ---- accumulator block layout (floats) ----
#define OFF_RD    0                       // N*2 : per-row sums of dsin,dcos (symmetric -> also col sums)
#define OFF_R1    2048                    // 6 arrays of N*32: R1,C1,R2,C2,R3,C3
#define OFF_SUMC  (2048 + 6*32768)        // 3 : sum_j cos(a_j)_d
#define OFF_SUMS  (OFF_SUMC + 3)          // 3 : sum_j sin(a_j)_d
#define OFF_UPS   (OFF_SUMS + 3)          // 3*64 : per-stage softplus-increment sums, up rows
#define OFF_DNS   (OFF_UPS + 192)         // 3*64 : down rows
#define ACC_TOTAL (OFF_DNS + 192)

__device__ float  g_acc[ACC_TOTAL];
__device__ float4 g_csn[2*NP];            // per particle: {c0,c1,c2,s0},{s1,s2,0,0}
__device__ float  g_sp[NP*64];

// ---- packed f32x2 helpers (Blackwell FFMA2 path) ----
__device__ __forceinline__ unsigned long long pk(float a, float b){
    unsigned long long r; asm("mov.b64 %0, {%1, %2};" : "=l"(r) : "f"(a), "f"(b)); return r;
}
__device__ __forceinline__ void unpk(unsigned long long v, float& a, float& b){
    asm("mov.b64 {%0, %1}, %2;" : "=f"(a), "=f"(b) : "l"(v));
}
__device__ __forceinline__ unsigned long long fma2(unsigned long long a, unsigned long long b, unsigned long long c){
    unsigned long long r; asm("fma.rn.f32x2 %0, %1, %2, %3;" : "=l"(r) : "l"(a), "l"(b), "l"(c)); return r;
}
__device__ __forceinline__ unsigned long long add2(unsigned long long a, unsigned long long b){
    unsigned long long r; asm("add.rn.f32x2 %0, %1, %2;" : "=l"(r) : "l"(a), "l"(b)); return r;
}
__device__ __forceinline__ float splus(float x){ return __logf(1.0f + __expf(x)); }

// ---- kernel 0: zero accumulators ----
__global__ void k_zero(){
    int i = blockIdx.x*blockDim.x + threadIdx.x;
    if (i < ACC_TOTAL) g_acc[i] = 0.0f;
}

// ---- kernel 1: per-particle cos/sin + global sums ----
__global__ void k_csn(const float* __restrict__ x){
    int i = blockIdx.x*blockDim.x + threadIdx.x;
    if (i >= NP) return;
    float c[3], s[3];
    #pragma unroll
    for (int d = 0; d < 3; d++){
        float a = TWOPI_L * x[i*3 + d];
        sincosf(a, &s[d], &c[d]);
        atomicAdd(&g_acc[OFF_SUMC + d], c[d]);
        atomicAdd(&g_acc[OFF_SUMS + d], s[d]);
    }
    g_csn[2*i]   = make_float4(c[0], c[1], c[2], s[0]);
    g_csn[2*i+1] = make_float4(s[1], s[2], 0.0f, 0.0f);
}

// ---- kernel 2: fused pairwise tp stream (both directions per anchor) ----
__global__ void __launch_bounds__(256, 1)
k_main(const float* __restrict__ tp_w0, const float* __restrict__ tp_b0,
       const float* __restrict__ tp_w,  const float* __restrict__ tp_b){
    __shared__ float4 shc[2*NP];                                    // 32 KB
    __shared__ __align__(16) unsigned long long hb[8][2][32];       //  4 KB

    const int tid  = threadIdx.x;
    const int lane = tid & 31;
    const int w    = tid >> 5;

    for (int idx = tid; idx < 2*NP; idx += 256) shc[idx] = g_csn[idx];
    __syncthreads();

    const int wg = blockIdx.x*8 + w;      // 4096 warp tasks
    const int i  = wg >> 2;               // anchor particle
    const int j0 = (wg & 3) * 256;        // quarter of partner range

    // weight columns in registers (packed {w,w} for f32x2)
    unsigned long long w0p[8], w1p[32], w2p[32];
    #pragma unroll
    for (int k = 0; k < 8;  k++){ float v = tp_w0[k*32 + lane];        w0p[k] = pk(v, v); }
    #pragma unroll
    for (int k = 0; k < 32; k++){ float v = tp_w[k*32 + lane];         w1p[k] = pk(v, v); }
    #pragma unroll
    for (int k = 0; k < 32; k++){ float v = tp_w[1024 + k*32 + lane];  w2p[k] = pk(v, v); }
    const unsigned long long b0p = pk(tp_b0[lane],    tp_b0[lane]);
    const unsigned long long b1p = pk(tp_b[lane],     tp_b[lane]);
    const unsigned long long b2p = pk(tp_b[32+lane],  tp_b[32+lane]);
    const unsigned long long Z = 0ull;   // {0.f, 0.f}

    const float4 Ai = shc[2*i], Bi = shc[2*i+1];
    const float ci0 = Ai.x, ci1 = Ai.y, ci2 = Ai.z;
    const float si0 = Ai.w, si1 = Bi.x, si2 = Bi.y;

    unsigned long long r1c1 = Z, r2c2 = Z, r3c3 = Z;
    float adsin = 0.0f, adcos = 0.0f;

    #pragma unroll 1
    for (int j = j0; j < j0 + 256; ++j){
        const float4 A = shc[2*j], B = shc[2*j+1];
        // angle-difference identities: c_d = cos(ai-aj), s_d = sin(ai-aj)
        float c0 = fmaf(ci0, A.x,  si0*A.w);
        float c1 = fmaf(ci1, A.y,  si1*B.x);
        float c2 = fmaf(ci2, A.z,  si2*B.y);
        float s0 = fmaf(si0, A.x, -ci0*A.w);
        float s1 = fmaf(si1, A.y, -ci1*B.x);
        float s2 = fmaf(si2, A.z, -ci2*B.y);
        float dsin = sqrtf(fmaf(s0, s0, fmaf(s1, s1, s2*s2)));
        float dcos = sqrtf(fmaf(c0, c0, fmaf(c1, c1, c2*c2)));
        if (j == i){ dsin = 0.0f; dcos = 0.0f; }
        adsin += dsin; adcos += dcos;

        // ---- layer 0 (8->32), fwd in low half, reverse (s negated) in high half
        unsigned long long acca, accb, z, h1, h2;
        float xf, xr;
        acca = fma2(pk(c0,  c0),  w0p[0], b0p);
        accb = fma2(pk(c1,  c1),  w0p[1], Z);
        acca = fma2(pk(c2,  c2),  w0p[2], acca);
        accb = fma2(pk(s0, -s0),  w0p[3], accb);
        acca = fma2(pk(s1, -s1),  w0p[4], acca);
        accb = fma2(pk(s2, -s2),  w0p[5], accb);
        acca = fma2(pk(dsin,dsin),w0p[6], acca);
        accb = fma2(pk(dcos,dcos),w0p[7], accb);
        z = add2(acca, accb);
        unpk(z, xf, xr);
        h1 = pk(splus(xf), splus(xr));          // tp1 (no residual at stage 0)
        r1c1 = add2(r1c1, h1);
        hb[w][0][lane] = h1;
        __syncwarp();

        // ---- layer 1 (32->32), residual
        acca = b1p; accb = Z;
        {
            const ulonglong2* p = (const ulonglong2*)(&hb[w][0][0]);
            #pragma unroll
            for (int kk = 0; kk < 16; ++kk){
                ulonglong2 v = p[kk];
                acca = fma2(v.x, w1p[2*kk],   acca);
                accb = fma2(v.y, w1p[2*kk+1], accb);
            }
        }
        z = add2(acca, accb);
        unpk(z, xf, xr);
        h2 = add2(h1, pk(splus(xf), splus(xr)));
        r2c2 = add2(r2c2, h2);
        hb[w][1][lane] = h2;
        __syncwarp();

        // ---- layer 2 (32->32), residual
        acca = b2p; accb = Z;
        {
            const ulonglong2* q = (const ulonglong2*)(&hb[w][1][0]);
            #pragma unroll
            for (int kk = 0; kk < 16; ++kk){
                ulonglong2 v = q[kk];
                acca = fma2(v.x, w2p[2*kk],   acca);
                accb = fma2(v.y, w2p[2*kk+1], accb);
            }
        }
        z = add2(acca, accb);
        unpk(z, xf, xr);
        unsigned long long h3 = add2(h2, pk(splus(xf), splus(xr)));
        r3c3 = add2(r3c3, h3);
    }

    // epilogue: low half -> row sums R[i], high half -> col sums C[i]
    float a, b;
    unpk(r1c1, a, b);
    atomicAdd(&g_acc[OFF_R1 + 0*32768 + i*32 + lane], a);
    atomicAdd(&g_acc[OFF_R1 + 1*32768 + i*32 + lane], b);
    unpk(r2c2, a, b);
    atomicAdd(&g_acc[OFF_R1 + 2*32768 + i*32 + lane], a);
    atomicAdd(&g_acc[OFF_R1 + 3*32768 + i*32 + lane], b);
    unpk(r3c3, a, b);
    atomicAdd(&g_acc[OFF_R1 + 4*32768 + i*32 + lane], a);
    atomicAdd(&g_acc[OFF_R1 + 5*32768 + i*32 + lane], b);
    if (lane == 0){
        atomicAdd(&g_acc[OFF_RD + 2*i],     adsin);
        atomicAdd(&g_acc[OFF_RD + 2*i + 1], adcos);
    }
}

// ---- kernel 3: one sp-stream stage (launched 4x, s = 0..3) ----
__global__ void k_stage(int s, const float* __restrict__ W, const float* __restrict__ bias,
                        const float* __restrict__ x, const float* __restrict__ finw,
                        const float* __restrict__ finb, float* __restrict__ out){
    __shared__ float sf[256];
    __shared__ float ssp[64];
    const int i = blockIdx.x;
    const int t = threadIdx.x;   // 0..63

    if (s == 0){
        if (t < 25) sf[t] = 0.0f;
        if (t == 0){
            float4 Ai = g_csn[2*i], Bi = g_csn[2*i+1];
            float ci[3] = {Ai.x, Ai.y, Ai.z};
            float si[3] = {Ai.w, Bi.x, Bi.y};
            #pragma unroll
            for (int d = 0; d < 3; d++){
                float Sc = g_acc[OFF_SUMC + d], Ss = g_acc[OFF_SUMS + d];
                float cm  = (ci[d]*Sc + si[d]*Ss) * INVN;   // row & col mean of c
                float smr = (si[d]*Sc - ci[d]*Ss) * INVN;   // row mean of s
                sf[9 + d]  = cm;   sf[12 + d] = smr;
                sf[17 + d] = cm;   sf[20 + d] = -smr;       // col mean of s is negated
            }
            float rd0 = g_acc[OFF_RD + 2*i]     * INVN;
            float rd1 = g_acc[OFF_RD + 2*i + 1] * INVN;
            sf[15] = rd0; sf[16] = rd1;                     // dsin/dcos symmetric
            sf[23] = rd0; sf[24] = rd1;
        }
    } else {
        sf[t] = g_sp[i*64 + t];                             // sp_prev
        float up = 0.0f, dn = 0.0f;
        for (int u = 0; u < s; ++u){
            up += g_acc[OFF_UPS + u*64 + t];
            dn += g_acc[OFF_DNS + u*64 + t];
        }
        sf[64 + t]  = up * (1.0f/NUP);
        sf[128 + t] = dn * (1.0f/NUP);
        if (t < 32){
            int ro = OFF_R1 + (s-1)*2*32768;
            sf[192 + t] = g_acc[ro + i*32 + t]          * INVN;   // row mean tp_s
            sf[224 + t] = g_acc[ro + 32768 + i*32 + t]  * INVN;   // col mean tp_s
        }
    }
    __syncthreads();

    const int indim = (s == 0) ? 25 : 256;
    float acc = bias[t];
    for (int k = 0; k < indim; ++k) acc = fmaf(sf[k], W[k*64 + t], acc);
    float v   = splus(acc);
    float spv = (s == 0) ? v : (sf[t] + v);
    g_sp[i*64 + t] = spv;

    if (s < 3){
        if (i < NUP) atomicAdd(&g_acc[OFF_UPS + s*64 + t], v);
        else         atomicAdd(&g_acc[OFF_DNS + s*64 + t], v);
    } else {
        ssp[t] = spv;
        __syncthreads();
        if (t < 3){
            float o = finb[t];
            #pragma unroll 4
            for (int k = 0; k < 64; ++k) o = fmaf(ssp[k], finw[k*3 + t], o);
            out[i*3 + t] = x[i*3 + t] + o;
        }
    }
}

extern "C" void kernel_launch(void* const* d_in, const int* in_sizes, int n_in,
                              void* d_out, int out_size){
    const float* x     = (const float*)d_in[0];
    const float* sp_w0 = (const float*)d_in[1];
    const float* sp_b0 = (const float*)d_in[2];
    const float* sp_w  = (const float*)d_in[3];
    const float* sp_b  = (const float*)d_in[4];
    const float* tp_w0 = (const float*)d_in[5];
    const float* tp_b0 = (const float*)d_in[6];
    const float* tp_w  = (const float*)d_in[7];
    const float* tp_b  = (const float*)d_in[8];
    const float* fin_w = (const float*)d_in[9];
    const float* fin_b = (const float*)d_in[10];
    float* out = (float*)d_out;

    k_zero<<<(ACC_TOTAL + 255)/256, 256>>>();
    k_csn <<<(NP + 255)/256, 256>>>(x);
    k_main<<<512, 256>>>(tp_w0, tp_b0, tp_w, tp_b);

    for (int s = 0; s < 4; ++s){
        const float* W = (s == 0) ? sp_w0 : (sp_w + (size_t)(s-1)*256*64);
        const float* b = (s == 0) ? sp_b0 : (sp_b + (size_t)(s-1)*64);
        k_stage<<<NP, 64>>>(s, W, b, x, fin_w, fin_b, out);
    }
}

// round 8
// speedup vs baseline: 2.5781x; 2.5781x over previous
#include <cuda_runtime.h>
#include <cstdint>

typedef unsigned long long u64;

#define NP 1024
#define NUP 512
#define TWOPI_L 0.6283185307179586f
#define INVN (1.0f/1024.0f)

// ---- accumulator block layout (floats) ----
#define OFF_RD    0                       // N*2 : per-row sums of dsin,dcos
#define OFF_R1    2048                    // 6 arrays of N*32: R1,C1,R2,C2,R3,C3
#define OFF_SUMC  (2048 + 6*32768)
#define OFF_SUMS  (OFF_SUMC + 3)
#define OFF_UPS   (OFF_SUMS + 3)
#define OFF_DNS   (OFF_UPS + 192)
#define ACC_TOTAL (OFF_DNS + 192)

__device__ float  g_acc[ACC_TOTAL];
__device__ float4 g_csn[2*NP];            // {c0,c1,c2,s0},{s1,s2,0,0}
__device__ float  g_sp[NP*64];

// ---- packed f32x2 helpers ----
__device__ __forceinline__ u64 pk(float a, float b){
    u64 r; asm("mov.b64 %0, {%1, %2};" : "=l"(r) : "f"(a), "f"(b)); return r;
}
__device__ __forceinline__ void unpk(u64 v, float& a, float& b){
    asm("mov.b64 {%0, %1}, %2;" : "=f"(a), "=f"(b) : "l"(v));
}
__device__ __forceinline__ u64 fma2(u64 a, u64 b, u64 c){
    u64 r; asm("fma.rn.f32x2 %0, %1, %2, %3;" : "=l"(r) : "l"(a), "l"(b), "l"(c)); return r;
}
__device__ __forceinline__ u64 add2(u64 a, u64 b){
    u64 r; asm("add.rn.f32x2 %0, %1, %2;" : "=l"(r) : "l"(a), "l"(b)); return r;
}
__device__ __forceinline__ u64 mul2(u64 a, u64 b){
    u64 r; asm("mul.rn.f32x2 %0, %1, %2;" : "=l"(r) : "l"(a), "l"(b)); return r;
}
__device__ __forceinline__ uint32_t tf32c(float v){
    uint32_t r; asm("cvt.rna.tf32.f32 %0, %1;" : "=r"(r) : "f"(v)); return r;
}
__device__ __forceinline__ float splus(float x){ return __logf(1.0f + __expf(x)); }

#define MMA8(c0,c1,c2,c3,a0,a1,a2,a3,b0,b1) \
  asm volatile("mma.sync.aligned.m16n8k8.row.col.f32.tf32.tf32.f32 " \
    "{%0,%1,%2,%3},{%4,%5,%6,%7},{%8,%9},{%0,%1,%2,%3};" \
    : "+f"(c0),"+f"(c1),"+f"(c2),"+f"(c3) \
    : "r"(a0),"r"(a1),"r"(a2),"r"(a3),"r"(b0),"r"(b1))

// packed softplus: ln2 + x/2 + x^2/8 - x^4/192 + x^6/2880  (valid |x|<~1)
__device__ __forceinline__ u64 splus2(u64 x, u64 C6, u64 C4, u64 C2, u64 LN2, u64 HALF){
    u64 u = mul2(x, x);
    u64 t = fma2(C6, u, C4);
    t = fma2(t, u, C2);
    t = fma2(t, u, LN2);
    return fma2(x, HALF, t);
}

// ---- kernel 0: zero accumulators ----
__global__ void k_zero(){
    int i = blockIdx.x*blockDim.x + threadIdx.x;
    if (i < ACC_TOTAL) g_acc[i] = 0.0f;
}

// ---- kernel 1: per-particle cos/sin + global sums ----
__global__ void k_csn(const float* __restrict__ x){
    int i = blockIdx.x*blockDim.x + threadIdx.x;
    if (i >= NP) return;
    float c[3], s[3];
    #pragma unroll
    for (int d = 0; d < 3; d++){
        float a = TWOPI_L * x[i*3 + d];
        sincosf(a, &s[d], &c[d]);
        atomicAdd(&g_acc[OFF_SUMC + d], c[d]);
        atomicAdd(&g_acc[OFF_SUMS + d], s[d]);
    }
    g_csn[2*i]   = make_float4(c[0], c[1], c[2], s[0]);
    g_csn[2*i+1] = make_float4(s[1], s[2], 0.0f, 0.0f);
}

// ---- kernel 2: tensor-core pairwise tp stream ----
// Grid 8192: block b -> anchor i = b>>3, seg = b&7 (seg<4 fwd rows, else rev).
// Block = 128 thr = 4 warps; each warp owns 64 pair-rows (M) x 32 features (N).
#define FPITCH 8
#define HPITCH 36

__global__ void __launch_bounds__(128)
k_mma(const float* __restrict__ tp_w0, const float* __restrict__ tp_b0,
      const float* __restrict__ tp_w,  const float* __restrict__ tp_b){
    __shared__ __align__(16) float sF[4*64*FPITCH];   //  8 KB
    __shared__ __align__(16) float sH[4*64*HPITCH];   // 36 KB

    const int tid  = threadIdx.x;
    const int lane = tid & 31;
    const int w    = tid >> 5;
    const int g    = lane >> 2;    // 0..7
    const int t    = lane & 3;     // 0..3

    const int blk = blockIdx.x;
    const int i   = blk >> 3;
    const int seg = blk & 7;
    const int dir = seg >> 2;                 // 0 fwd (row sums), 1 rev (col sums)
    const int j0  = (seg & 3) * 256 + w * 64; // first partner for this warp
    const float sgn = dir ? -1.0f : 1.0f;

    float* Fw = sF + w*64*FPITCH;
    float* Hw = sH + w*64*HPITCH;

    // ---- B fragments in registers (tf32) ----
    // mma m16n8k8 B (col-major k8 x n8): lane -> b0=(k=t, n=g), b1=(k=t+4, n=g)
    uint32_t B0[4][2], BB[2][4][4][2];   // B0[nt], BB[L][nt][ks]
    #pragma unroll
    for (int nt = 0; nt < 4; nt++){
        int n = nt*8 + g;
        B0[nt][0] = tf32c(tp_w0[t*32 + n]);
        B0[nt][1] = tf32c(tp_w0[(t+4)*32 + n]);
        #pragma unroll
        for (int ks = 0; ks < 4; ks++){
            BB[0][nt][ks][0] = tf32c(tp_w[(ks*8 + t)*32 + n]);
            BB[0][nt][ks][1] = tf32c(tp_w[(ks*8 + t + 4)*32 + n]);
            BB[1][nt][ks][0] = tf32c(tp_w[1024 + (ks*8 + t)*32 + n]);
            BB[1][nt][ks][1] = tf32c(tp_w[1024 + (ks*8 + t + 4)*32 + n]);
        }
    }
    // bias pairs at C columns (2t, 2t+1) per ntile
    u64 bias0[4], bs12[2][4];
    #pragma unroll
    for (int nt = 0; nt < 4; nt++){
        int c0 = nt*8 + 2*t;
        bias0[nt]    = pk(tp_b0[c0],      tp_b0[c0+1]);
        bs12[0][nt]  = pk(tp_b[c0],       tp_b[c0+1]);
        bs12[1][nt]  = pk(tp_b[32+c0],    tp_b[32+c0+1]);
    }
    const u64 P_C6  = pk( 3.4722222e-4f,  3.4722222e-4f);
    const u64 P_C4  = pk(-5.2083335e-3f, -5.2083335e-3f);
    const u64 P_C2  = pk( 0.125f,         0.125f);
    const u64 P_LN2 = pk( 0.69314718f,    0.69314718f);
    const u64 P_HF  = pk( 0.5f,           0.5f);

    // ---- features for this warp's 64 rows ----
    const float4 Ai = g_csn[2*i], Bi = g_csn[2*i+1];
    float adsin = 0.0f, adcos = 0.0f;
    #pragma unroll
    for (int rr = 0; rr < 2; rr++){
        int rl = lane + rr*32;
        int j  = j0 + rl;
        float4 A = g_csn[2*j], B = g_csn[2*j+1];
        float c0 = fmaf(Ai.x, A.x,  Ai.w*A.w);
        float c1 = fmaf(Ai.y, A.y,  Bi.x*B.x);
        float c2 = fmaf(Ai.z, A.z,  Bi.y*B.y);
        float s0 = fmaf(Ai.w, A.x, -Ai.x*A.w);
        float s1 = fmaf(Bi.x, A.y, -Ai.y*B.x);
        float s2 = fmaf(Bi.y, A.z, -Ai.z*B.y);
        float dsin = sqrtf(fmaf(s0,s0, fmaf(s1,s1, s2*s2)));
        float dcos = sqrtf(fmaf(c0,c0, fmaf(c1,c1, c2*c2)));
        if (j == i){ dsin = 0.0f; dcos = 0.0f; }
        adsin += dsin; adcos += dcos;
        float* fp = Fw + rl*FPITCH;
        fp[0]=c0; fp[1]=c1; fp[2]=c2;
        fp[3]=sgn*s0; fp[4]=sgn*s1; fp[5]=sgn*s2;
        fp[6]=dsin; fp[7]=dcos;
    }
    __syncwarp();

    u64 rs[3][4];
    #pragma unroll
    for (int l = 0; l < 3; l++)
        #pragma unroll
        for (int nt = 0; nt < 4; nt++) rs[l][nt] = 0ull;

    // ---- layer 0: F(64x8) @ W0(8x32) -> softplus -> H1 ----
    #pragma unroll
    for (int mt = 0; mt < 4; mt++){
        int rm = mt*16;
        const float* fa = Fw + (rm+g)*FPITCH + t;
        uint32_t a0 = __float_as_uint(fa[0]);
        uint32_t a1 = __float_as_uint(fa[8*FPITCH]);
        uint32_t a2 = __float_as_uint(fa[4]);
        uint32_t a3 = __float_as_uint(fa[8*FPITCH + 4]);
        #pragma unroll
        for (int nt = 0; nt < 4; nt++){
            float c0=0.f, c1=0.f, c2=0.f, c3=0.f;
            MMA8(c0,c1,c2,c3, a0,a1,a2,a3, B0[nt][0], B0[nt][1]);
            u64 x01 = add2(pk(c0,c1), bias0[nt]);
            u64 x23 = add2(pk(c2,c3), bias0[nt]);
            u64 h01 = splus2(x01, P_C6,P_C4,P_C2,P_LN2,P_HF);
            u64 h23 = splus2(x23, P_C6,P_C4,P_C2,P_LN2,P_HF);
            float* hp = Hw + (rm+g)*HPITCH + nt*8 + 2*t;
            *reinterpret_cast<u64*>(hp)             = h01;
            *reinterpret_cast<u64*>(hp + 8*HPITCH)  = h23;
            rs[0][nt] = add2(rs[0][nt], add2(h01, h23));
        }
    }
    __syncwarp();

    // ---- layers 1,2: H @ W(32x32) -> +bias -> softplus -> residual add ----
    #pragma unroll
    for (int L = 0; L < 2; L++){
        #pragma unroll
        for (int mt = 0; mt < 4; mt++){
            int rm = mt*16;
            float C[4][4];
            #pragma unroll
            for (int nt = 0; nt < 4; nt++){
                C[nt][0]=0.f; C[nt][1]=0.f; C[nt][2]=0.f; C[nt][3]=0.f;
            }
            #pragma unroll
            for (int ks = 0; ks < 4; ks++){
                const float* ha = Hw + (rm+g)*HPITCH + ks*8 + t;
                uint32_t a0 = __float_as_uint(ha[0]);
                uint32_t a1 = __float_as_uint(ha[8*HPITCH]);
                uint32_t a2 = __float_as_uint(ha[4]);
                uint32_t a3 = __float_as_uint(ha[8*HPITCH + 4]);
                #pragma unroll
                for (int nt = 0; nt < 4; nt++)
                    MMA8(C[nt][0],C[nt][1],C[nt][2],C[nt][3],
                         a0,a1,a2,a3, BB[L][nt][ks][0], BB[L][nt][ks][1]);
            }
            __syncwarp();   // all in-place reads of this mtile's rows done
            #pragma unroll
            for (int nt = 0; nt < 4; nt++){
                u64 x01 = add2(pk(C[nt][0], C[nt][1]), bs12[L][nt]);
                u64 x23 = add2(pk(C[nt][2], C[nt][3]), bs12[L][nt]);
                u64 s01 = splus2(x01, P_C6,P_C4,P_C2,P_LN2,P_HF);
                u64 s23 = splus2(x23, P_C6,P_C4,P_C2,P_LN2,P_HF);
                float* hp = Hw + (rm+g)*HPITCH + nt*8 + 2*t;
                u64 h01 = add2(*reinterpret_cast<const u64*>(hp),            s01);
                u64 h23 = add2(*reinterpret_cast<const u64*>(hp + 8*HPITCH), s23);
                *reinterpret_cast<u64*>(hp)            = h01;
                *reinterpret_cast<u64*>(hp + 8*HPITCH) = h23;
                rs[L+1][nt] = add2(rs[L+1][nt], add2(h01, h23));
            }
        }
        __syncwarp();
    }

    // ---- reduce rowsums over g (butterfly), atomically accumulate ----
    #pragma unroll
    for (int l = 0; l < 3; l++){
        #pragma unroll
        for (int nt = 0; nt < 4; nt++){
            u64 v = rs[l][nt];
            v = add2(v, __shfl_xor_sync(0xffffffffu, v, 4));
            v = add2(v, __shfl_xor_sync(0xffffffffu, v, 8));
            v = add2(v, __shfl_xor_sync(0xffffffffu, v, 16));
            if (lane < 4){
                float a, b; unpk(v, a, b);
                int base = OFF_R1 + l*65536 + dir*32768 + i*32 + nt*8 + 2*t;
                atomicAdd(&g_acc[base],   a);
                atomicAdd(&g_acc[base+1], b);
            }
        }
    }
    if (!dir){
        #pragma unroll
        for (int off = 16; off; off >>= 1){
            adsin += __shfl_xor_sync(0xffffffffu, adsin, off);
            adcos += __shfl_xor_sync(0xffffffffu, adcos, off);
        }
        if (lane == 0){
            atomicAdd(&g_acc[OFF_RD + 2*i],     adsin);
            atomicAdd(&g_acc[OFF_RD + 2*i + 1], adcos);
        }
    }
}

// ---- kernel 3: sp-stream stage (256 thr, split-4 dot) ----
__global__ void k_stage(int s, const float* __restrict__ W, const float* __restrict__ bias,
                        const float* __restrict__ x, const float* __restrict__ finw,
                        const float* __restrict__ finb, float* __restrict__ out){
    __shared__ float sf[256];
    __shared__ float red[256];
    __shared__ float ssp[64];
    const int i   = blockIdx.x;
    const int tid = threadIdx.x;
    const int t   = tid & 63;
    const int q   = tid >> 6;

    if (s == 0){
        if (tid < 25) sf[tid] = 0.0f;
        if (tid == 0){
            float4 Ai = g_csn[2*i], Bi = g_csn[2*i+1];
            float ci[3] = {Ai.x, Ai.y, Ai.z};
            float si[3] = {Ai.w, Bi.x, Bi.y};
            #pragma unroll
            for (int d = 0; d < 3; d++){
                float Sc = g_acc[OFF_SUMC + d], Ss = g_acc[OFF_SUMS + d];
                float cm  = (ci[d]*Sc + si[d]*Ss) * INVN;
                float smr = (si[d]*Sc - ci[d]*Ss) * INVN;
                sf[9 + d]  = cm;   sf[12 + d] = smr;
                sf[17 + d] = cm;   sf[20 + d] = -smr;
            }
            float rd0 = g_acc[OFF_RD + 2*i]     * INVN;
            float rd1 = g_acc[OFF_RD + 2*i + 1] * INVN;
            sf[15] = rd0; sf[16] = rd1;
            sf[23] = rd0; sf[24] = rd1;
        }
    } else {
        if (tid < 64){
            sf[tid] = g_sp[i*64 + tid];
            float up = 0.0f, dn = 0.0f;
            for (int u = 0; u < s; ++u){
                up += g_acc[OFF_UPS + u*64 + tid];
                dn += g_acc[OFF_DNS + u*64 + tid];
            }
            sf[64 + tid]  = up * (1.0f/NUP);
            sf[128 + tid] = dn * (1.0f/NUP);
        } else if (tid < 96){
            int tt = tid - 64;
            int ro = OFF_R1 + (s-1)*65536;
            sf[192 + tt] = g_acc[ro + i*32 + tt]         * INVN;
            sf[224 + tt] = g_acc[ro + 32768 + i*32 + tt] * INVN;
        }
    }
    __syncthreads();

    const int indim = (s == 0) ? 25 : 256;
    int k0 = q*64, k1 = min(indim, k0 + 64);
    float acc = (q == 0) ? bias[t] : 0.0f;
    for (int k = k0; k < k1; ++k) acc = fmaf(sf[k], W[k*64 + t], acc);
    red[tid] = acc;
    __syncthreads();

    if (tid < 64){
        acc = red[tid] + red[tid+64] + red[tid+128] + red[tid+192];
        float v   = splus(acc);
        float spv = (s == 0) ? v : (sf[tid] + v);
        g_sp[i*64 + tid] = spv;
        if (s < 3){
            if (i < NUP) atomicAdd(&g_acc[OFF_UPS + s*64 + tid], v);
            else         atomicAdd(&g_acc[OFF_DNS + s*64 + tid], v);
        } else {
            ssp[tid] = spv;
        }
    }
    if (s == 3){
        __syncthreads();
        if (tid < 3){
            float o = finb[tid];
            #pragma unroll 4
            for (int k = 0; k < 64; ++k) o = fmaf(ssp[k], finw[k*3 + tid], o);
            out[i*3 + tid] = x[i*3 + tid] + o;
        }
    }
}

extern "C" void kernel_launch(void* const* d_in, const int* in_sizes, int n_in,
                              void* d_out, int out_size){
    const float* x     = (const float*)d_in[0];
    const float* sp_w0 = (const float*)d_in[1];
    const float* sp_b0 = (const float*)d_in[2];
    const float* sp_w  = (const float*)d_in[3];
    const float* sp_b  = (const float*)d_in[4];
    const float* tp_w0 = (const float*)d_in[5];
    const float* tp_b0 = (const float*)d_in[6];
    const float* tp_w  = (const float*)d_in[7];
    const float* tp_b  = (const float*)d_in[8];
    const float* fin_w = (const float*)d_in[9];
    const float* fin_b = (const float*)d_in[10];
    float* out = (float*)d_out;

    k_zero<<<(ACC_TOTAL + 255)/256, 256>>>();
    k_csn <<<(NP + 255)/256, 256>>>(x);
    k_mma <<<NP*8, 128>>>(tp_w0, tp_b0, tp_w, tp_b);

    for (int s = 0; s < 4; ++s){
        const float* W = (s == 0) ? sp_w0 : (sp_w + (size_t)(s-1)*256*64);
        const float* b = (s == 0) ? sp_b0 : (sp_b + (size_t)(s-1)*64);
        k_stage<<<NP, 256>>>(s, W, b, x, fin_w, fin_b, out);
    }
}

// round 9
// speedup vs baseline: 3.1735x; 1.2309x over previous
#include <cuda_runtime.h>
#include <cstdint>

typedef unsigned long long u64;

#define NP 1024
#define NUP 512
#define TWOPI_L 0.6283185307179586f
#define INVN (1.0f/1024.0f)

// ---- accumulator block layout (floats) ----
#define OFF_RD    0                       // N*2 : per-row sums of dsin,dcos
#define OFF_R1    2048                    // 6 arrays of N*32: R1,C1,R2,C2,R3,C3
#define OFF_SUMC  (2048 + 6*32768)
#define OFF_SUMS  (OFF_SUMC + 3)
#define OFF_UPS   (OFF_SUMS + 3)
#define OFF_DNS   (OFF_UPS + 192)
#define ACC_TOTAL (OFF_DNS + 192)

__device__ float  g_acc[ACC_TOTAL];
__device__ float4 g_csn[2*NP];            // {c0,c1,c2,s0},{s1,s2,0,0}
__device__ float  g_sp[NP*64];

// ---- packed f32x2 helpers ----
__device__ __forceinline__ u64 pk(float a, float b){
    u64 r; asm("mov.b64 %0, {%1, %2};" : "=l"(r) : "f"(a), "f"(b)); return r;
}
__device__ __forceinline__ void unpk(u64 v, float& a, float& b){
    asm("mov.b64 {%0, %1}, %2;" : "=f"(a), "=f"(b) : "l"(v));
}
__device__ __forceinline__ u64 fma2(u64 a, u64 b, u64 c){
    u64 r; asm("fma.rn.f32x2 %0, %1, %2, %3;" : "=l"(r) : "l"(a), "l"(b), "l"(c)); return r;
}
__device__ __forceinline__ u64 add2(u64 a, u64 b){
    u64 r; asm("add.rn.f32x2 %0, %1, %2;" : "=l"(r) : "l"(a), "l"(b)); return r;
}
__device__ __forceinline__ u64 mul2(u64 a, u64 b){
    u64 r; asm("mul.rn.f32x2 %0, %1, %2;" : "=l"(r) : "l"(a), "l"(b)); return r;
}
__device__ __forceinline__ uint32_t tf32c(float v){
    uint32_t r; asm("cvt.rna.tf32.f32 %0, %1;" : "=r"(r) : "f"(v)); return r;
}
// pack two f32 -> bf16x2 (lo = first elem)
__device__ __forceinline__ uint32_t pkbf(float lo, float hi){
    uint32_t r; asm("cvt.rn.bf16x2.f32 %0, %1, %2;" : "=r"(r) : "f"(hi), "f"(lo)); return r;
}
// f32x2 (u64) -> bf16x2 (u32)
__device__ __forceinline__ uint32_t f2bf(u64 v){
    float a, b; unpk(v, a, b);
    uint32_t r; asm("cvt.rn.bf16x2.f32 %0, %1, %2;" : "=r"(r) : "f"(b), "f"(a)); return r;
}
// bf16x2 (u32) -> f32x2 (u64)
__device__ __forceinline__ u64 bf2f2(uint32_t u){
    uint32_t lo = u << 16, hi = u & 0xffff0000u;
    u64 r; asm("mov.b64 %0, {%1, %2};" : "=l"(r) : "r"(lo), "r"(hi)); return r;
}
__device__ __forceinline__ float splus(float x){ return __logf(1.0f + __expf(x)); }

#define MMAT(c0,c1,c2,c3,a0,a1,a2,a3,b0,b1) \
  asm volatile("mma.sync.aligned.m16n8k8.row.col.f32.tf32.tf32.f32 " \
    "{%0,%1,%2,%3},{%4,%5,%6,%7},{%8,%9},{%0,%1,%2,%3};" \
    : "+f"(c0),"+f"(c1),"+f"(c2),"+f"(c3) \
    : "r"(a0),"r"(a1),"r"(a2),"r"(a3),"r"(b0),"r"(b1))

#define MMAB(c0,c1,c2,c3,a0,a1,a2,a3,b0,b1) \
  asm volatile("mma.sync.aligned.m16n8k16.row.col.f32.bf16.bf16.f32 " \
    "{%0,%1,%2,%3},{%4,%5,%6,%7},{%8,%9},{%0,%1,%2,%3};" \
    : "+f"(c0),"+f"(c1),"+f"(c2),"+f"(c3) \
    : "r"(a0),"r"(a1),"r"(a2),"r"(a3),"r"(b0),"r"(b1))

// packed softplus, 4th order: ln2 + x/2 + x^2/8 - x^4/192   (|x|<~0.5)
__device__ __forceinline__ u64 splus4(u64 x, u64 C4, u64 C2, u64 LN2, u64 HALF){
    u64 u = mul2(x, x);
    u64 t = fma2(C4, u, C2);
    t = fma2(t, u, LN2);
    return fma2(x, HALF, t);
}

// ---- kernel 0: zero accumulators ----
__global__ void k_zero(){
    int i = blockIdx.x*blockDim.x + threadIdx.x;
    if (i < ACC_TOTAL) g_acc[i] = 0.0f;
}

// ---- kernel 1: per-particle cos/sin + global sums ----
__global__ void k_csn(const float* __restrict__ x){
    int i = blockIdx.x*blockDim.x + threadIdx.x;
    if (i >= NP) return;
    float c[3], s[3];
    #pragma unroll
    for (int d = 0; d < 3; d++){
        float a = TWOPI_L * x[i*3 + d];
        sincosf(a, &s[d], &c[d]);
        atomicAdd(&g_acc[OFF_SUMC + d], c[d]);
        atomicAdd(&g_acc[OFF_SUMS + d], s[d]);
    }
    g_csn[2*i]   = make_float4(c[0], c[1], c[2], s[0]);
    g_csn[2*i+1] = make_float4(s[1], s[2], 0.0f, 0.0f);
}

// ---- kernel 2: tensor-core pairwise tp stream ----
// Grid 8192: block b -> anchor i = b>>3, seg = b&7 (seg<4 fwd, else rev).
// 4 warps/block, each warp: 64 pair-rows x 32 features, 3-layer MLP.
#define PIT  20     // u32 pitch of bf16x2 H buffers (conflict-free)
#define FPIT 12     // f32 pitch of feature buffer (conflict-free)

__global__ void __launch_bounds__(128)
k_mma(const float* __restrict__ tp_w0, const float* __restrict__ tp_b0,
      const float* __restrict__ tp_w,  const float* __restrict__ tp_b){
    __shared__ __align__(16) uint32_t sB[4][2][64*PIT];   // 40 KB
    __shared__ float sRS[4][96];
    __shared__ float sAD[4][2];

    const int tid  = threadIdx.x;
    const int lane = tid & 31;
    const int w    = tid >> 5;
    const int g    = lane >> 2;    // 0..7
    const int t    = lane & 3;     // 0..3

    const int blk = blockIdx.x;
    const int i   = blk >> 3;
    const int seg = blk & 7;
    const int dir = seg >> 2;                 // 0 fwd (row sums), 1 rev (col sums)
    const int j0  = (seg & 3) * 256 + w * 64;
    const float sgn = dir ? -1.0f : 1.0f;

    uint32_t* Hb0 = sB[w][0];
    uint32_t* Hb1 = sB[w][1];
    float*    Fw  = reinterpret_cast<float*>(sB[w][1]);   // aliased: dead before Hb1 written

    // ---- weight fragments ----
    uint32_t B0[4][2];               // layer0 tf32 B (k8)
    uint32_t BB[2][4][2][2];         // layers 1,2 bf16 B: [L][nt][kchunk][reg]
    float blo[3][4], bhi[3][4];      // bias at C cols (2t, 2t+1)
    #pragma unroll
    for (int nt = 0; nt < 4; nt++){
        int n = nt*8 + g;
        B0[nt][0] = tf32c(tp_w0[t*32 + n]);
        B0[nt][1] = tf32c(tp_w0[(t+4)*32 + n]);
        #pragma unroll
        for (int L = 0; L < 2; L++){
            const float* W = tp_w + L*1024;
            #pragma unroll
            for (int c = 0; c < 2; c++){
                BB[L][nt][c][0] = pkbf(W[(c*16 + 2*t    )*32 + n], W[(c*16 + 2*t + 1)*32 + n]);
                BB[L][nt][c][1] = pkbf(W[(c*16 + 2*t + 8)*32 + n], W[(c*16 + 2*t + 9)*32 + n]);
            }
        }
        int c0 = nt*8 + 2*t;
        blo[0][nt] = tp_b0[c0];     bhi[0][nt] = tp_b0[c0+1];
        blo[1][nt] = tp_b[c0];      bhi[1][nt] = tp_b[c0+1];
        blo[2][nt] = tp_b[32+c0];   bhi[2][nt] = tp_b[32+c0+1];
    }
    const u64 P_C4  = pk(-5.2083335e-3f, -5.2083335e-3f);
    const u64 P_C2  = pk( 0.125f,         0.125f);
    const u64 P_LN2 = pk( 0.69314718f,    0.69314718f);
    const u64 P_HF  = pk( 0.5f,           0.5f);

    // ---- features for this warp's 64 rows ----
    const float4 Ai = g_csn[2*i], Bi = g_csn[2*i+1];
    float adsin = 0.0f, adcos = 0.0f;
    #pragma unroll
    for (int rr = 0; rr < 2; rr++){
        int rl = lane + rr*32;
        int j  = j0 + rl;
        float4 A = g_csn[2*j], B = g_csn[2*j+1];
        float c0 = fmaf(Ai.x, A.x,  Ai.w*A.w);
        float c1 = fmaf(Ai.y, A.y,  Bi.x*B.x);
        float c2 = fmaf(Ai.z, A.z,  Bi.y*B.y);
        float s0 = fmaf(Ai.w, A.x, -Ai.x*A.w);
        float s1 = fmaf(Bi.x, A.y, -Ai.y*B.x);
        float s2 = fmaf(Bi.y, A.z, -Ai.z*B.y);
        float dsin = sqrtf(fmaf(s0,s0, fmaf(s1,s1, s2*s2)));
        float dcos = sqrtf(fmaf(c0,c0, fmaf(c1,c1, c2*c2)));
        if (j == i){ dsin = 0.0f; dcos = 0.0f; }
        adsin += dsin; adcos += dcos;
        float* fp = Fw + rl*FPIT;
        fp[0]=c0; fp[1]=c1; fp[2]=c2;
        fp[3]=sgn*s0; fp[4]=sgn*s1; fp[5]=sgn*s2;
        fp[6]=dsin; fp[7]=dcos;
    }
    __syncwarp();

    u64 rs[3][4];
    #pragma unroll
    for (int l = 0; l < 3; l++)
        #pragma unroll
        for (int nt = 0; nt < 4; nt++) rs[l][nt] = 0ull;

    // ---- layer 0: tf32, F(64x8) @ W0 -> softplus -> Hb0 (bf16) ----
    #pragma unroll
    for (int mt = 0; mt < 4; mt++){
        int rm = mt*16;
        const float* fa = Fw + (rm+g)*FPIT + t;
        uint32_t a0 = __float_as_uint(fa[0]);
        uint32_t a1 = __float_as_uint(fa[8*FPIT]);
        uint32_t a2 = __float_as_uint(fa[4]);
        uint32_t a3 = __float_as_uint(fa[8*FPIT + 4]);
        #pragma unroll
        for (int nt = 0; nt < 4; nt++){
            float c0 = blo[0][nt], c1 = bhi[0][nt], c2 = blo[0][nt], c3 = bhi[0][nt];
            MMAT(c0,c1,c2,c3, a0,a1,a2,a3, B0[nt][0], B0[nt][1]);
            u64 h01 = splus4(pk(c0,c1), P_C4,P_C2,P_LN2,P_HF);
            u64 h23 = splus4(pk(c2,c3), P_C4,P_C2,P_LN2,P_HF);
            rs[0][nt] = add2(rs[0][nt], add2(h01, h23));
            int pidx = nt*4 + t;
            Hb0[(rm+g  )*PIT + pidx] = f2bf(h01);
            Hb0[(rm+g+8)*PIT + pidx] = f2bf(h23);
        }
    }
    __syncwarp();

    // ---- layers 1,2: bf16 m16n8k16, residual in f32 ----
    #pragma unroll
    for (int L = 0; L < 2; L++){
        uint32_t* Rd = (L == 0) ? Hb0 : Hb1;
        uint32_t* Wr = Hb1;   // only used when L==0
        #pragma unroll
        for (int mt = 0; mt < 4; mt++){
            int rm = mt*16;
            float C[4][4];
            #pragma unroll
            for (int nt = 0; nt < 4; nt++){
                C[nt][0] = blo[L+1][nt]; C[nt][1] = bhi[L+1][nt];
                C[nt][2] = blo[L+1][nt]; C[nt][3] = bhi[L+1][nt];
            }
            #pragma unroll
            for (int c = 0; c < 2; c++){
                int ro = (rm+g)*PIT + c*8 + t;
                uint32_t a0 = Rd[ro];
                uint32_t a1 = Rd[ro + 8*PIT];
                uint32_t a2 = Rd[ro + 4];
                uint32_t a3 = Rd[ro + 8*PIT + 4];
                #pragma unroll
                for (int nt = 0; nt < 4; nt++)
                    MMAB(C[nt][0],C[nt][1],C[nt][2],C[nt][3],
                         a0,a1,a2,a3, BB[L][nt][c][0], BB[L][nt][c][1]);
            }
            #pragma unroll
            for (int nt = 0; nt < 4; nt++){
                int pidx = nt*4 + t;
                int r0 = (rm+g)*PIT + pidx, r1 = r0 + 8*PIT;
                u64 s01 = splus4(pk(C[nt][0], C[nt][1]), P_C4,P_C2,P_LN2,P_HF);
                u64 s23 = splus4(pk(C[nt][2], C[nt][3]), P_C4,P_C2,P_LN2,P_HF);
                u64 h01 = add2(bf2f2(Rd[r0]), s01);
                u64 h23 = add2(bf2f2(Rd[r1]), s23);
                rs[L+1][nt] = add2(rs[L+1][nt], add2(h01, h23));
                if (L == 0){
                    Wr[r0] = f2bf(h01);
                    Wr[r1] = f2bf(h23);
                }
            }
        }
        __syncwarp();
    }

    // ---- reduce rowsums over g (shfl), then across warps in smem ----
    #pragma unroll
    for (int l = 0; l < 3; l++){
        #pragma unroll
        for (int nt = 0; nt < 4; nt++){
            u64 v = rs[l][nt];
            v = add2(v, __shfl_xor_sync(0xffffffffu, v, 4));
            v = add2(v, __shfl_xor_sync(0xffffffffu, v, 8));
            v = add2(v, __shfl_xor_sync(0xffffffffu, v, 16));
            if (lane < 4){
                float a, b; unpk(v, a, b);
                sRS[w][l*32 + nt*8 + 2*t]     = a;
                sRS[w][l*32 + nt*8 + 2*t + 1] = b;
            }
        }
    }
    #pragma unroll
    for (int off = 16; off; off >>= 1){
        adsin += __shfl_xor_sync(0xffffffffu, adsin, off);
        adcos += __shfl_xor_sync(0xffffffffu, adcos, off);
    }
    if (lane == 0){ sAD[w][0] = adsin; sAD[w][1] = adcos; }
    __syncthreads();
    if (tid < 96){
        float v = sRS[0][tid] + sRS[1][tid] + sRS[2][tid] + sRS[3][tid];
        int l = tid >> 5, col = tid & 31;
        atomicAdd(&g_acc[OFF_R1 + l*65536 + dir*32768 + i*32 + col], v);
    }
    if (!dir && tid < 2){
        float v = sAD[0][tid] + sAD[1][tid] + sAD[2][tid] + sAD[3][tid];
        atomicAdd(&g_acc[OFF_RD + 2*i + tid], v);
    }
}

// ---- kernel 3a: sp-stream stage 0 (per-particle blocks; indim=25, cheap) ----
__global__ void k_stage0(const float* __restrict__ W, const float* __restrict__ bias,
                         const float* __restrict__ x){
    __shared__ float sf[256];
    __shared__ float red[256];
    const int i   = blockIdx.x;
    const int tid = threadIdx.x;
    const int t   = tid & 63;
    const int q   = tid >> 6;

    if (tid < 25) sf[tid] = 0.0f;
    if (tid == 0){
        float4 Ai = g_csn[2*i], Bi = g_csn[2*i+1];
        float ci[3] = {Ai.x, Ai.y, Ai.z};
        float si[3] = {Ai.w, Bi.x, Bi.y};
        #pragma unroll
        for (int d = 0; d < 3; d++){
            float Sc = g_acc[OFF_SUMC + d], Ss = g_acc[OFF_SUMS + d];
            float cm  = (ci[d]*Sc + si[d]*Ss) * INVN;
            float smr = (si[d]*Sc - ci[d]*Ss) * INVN;
            sf[9 + d]  = cm;   sf[12 + d] = smr;
            sf[17 + d] = cm;   sf[20 + d] = -smr;
        }
        float rd0 = g_acc[OFF_RD + 2*i]     * INVN;
        float rd1 = g_acc[OFF_RD + 2*i + 1] * INVN;
        sf[15] = rd0; sf[16] = rd1;
        sf[23] = rd0; sf[24] = rd1;
    }
    __syncthreads();

    int k0 = q*64, k1 = min(25, k0 + 64);
    float acc = (q == 0) ? bias[t] : 0.0f;
    for (int k = k0; k < k1; ++k) acc = fmaf(sf[k], W[k*64 + t], acc);
    red[tid] = acc;
    __syncthreads();

    if (tid < 64){
        acc = red[tid] + red[tid+64] + red[tid+128] + red[tid+192];
        float v = splus(acc);
        g_sp[i*64 + tid] = v;
        if (i < NUP) atomicAdd(&g_acc[OFF_UPS + tid], v);
        else         atomicAdd(&g_acc[OFF_DNS + tid], v);
    }
}

// ---- kernel 3b: sp-stream stages 1..3 — 8 particles/block, W in registers ----
__global__ void __launch_bounds__(256)
k_stageN(int s, const float* __restrict__ W, const float* __restrict__ bias,
         const float* __restrict__ x, const float* __restrict__ finw,
         const float* __restrict__ finb, float* __restrict__ out){
    __shared__ float sf[256];
    __shared__ float red[256];
    __shared__ float ssp[64];
    const int tid = threadIdx.x;
    const int t   = tid & 63;
    const int q   = tid >> 6;

    float wreg[64];
    #pragma unroll 8
    for (int k = 0; k < 64; ++k) wreg[k] = W[(q*64 + k)*64 + t];
    const float bv = bias[t];

    for (int p = 0; p < 8; ++p){
        const int i = blockIdx.x*8 + p;
        if (tid < 64){
            sf[tid] = g_sp[i*64 + tid];
            float up = 0.0f, dn = 0.0f;
            for (int u = 0; u < s; ++u){
                up += g_acc[OFF_UPS + u*64 + tid];
                dn += g_acc[OFF_DNS + u*64 + tid];
            }
            sf[64 + tid]  = up * (1.0f/NUP);
            sf[128 + tid] = dn * (1.0f/NUP);
        } else if (tid < 96){
            int tt = tid - 64;
            int ro = OFF_R1 + (s-1)*65536;
            sf[192 + tt] = g_acc[ro + i*32 + tt]         * INVN;
            sf[224 + tt] = g_acc[ro + 32768 + i*32 + tt] * INVN;
        }
        __syncthreads();

        float acc = (q == 0) ? bv : 0.0f;
        #pragma unroll 16
        for (int k = 0; k < 64; ++k) acc = fmaf(sf[q*64 + k], wreg[k], acc);
        red[tid] = acc;
        __syncthreads();

        if (tid < 64){
            acc = red[tid] + red[tid+64] + red[tid+128] + red[tid+192];
            float v   = splus(acc);
            float spv = sf[tid] + v;
            g_sp[i*64 + tid] = spv;
            if (s < 3){
                if (i < NUP) atomicAdd(&g_acc[OFF_UPS + s*64 + tid], v);
                else         atomicAdd(&g_acc[OFF_DNS + s*64 + tid], v);
            } else {
                ssp[tid] = spv;
            }
        }
        __syncthreads();
        if (s == 3 && tid < 3){
            float o = finb[tid];
            #pragma unroll 4
            for (int k = 0; k < 64; ++k) o = fmaf(ssp[k], finw[k*3 + tid], o);
            out[i*3 + tid] = x[i*3 + tid] + o;
        }
        __syncthreads();
    }
}

extern "C" void kernel_launch(void* const* d_in, const int* in_sizes, int n_in,
                              void* d_out, int out_size){
    const float* x     = (const float*)d_in[0];
    const float* sp_w0 = (const float*)d_in[1];
    const float* sp_b0 = (const float*)d_in[2];
    const float* sp_w  = (const float*)d_in[3];
    const float* sp_b  = (const float*)d_in[4];
    const float* tp_w0 = (const float*)d_in[5];
    const float* tp_b0 = (const float*)d_in[6];
    const float* tp_w  = (const float*)d_in[7];
    const float* tp_b  = (const float*)d_in[8];
    const float* fin_w = (const float*)d_in[9];
    const float* fin_b = (const float*)d_in[10];
    float* out = (float*)d_out;

    k_zero<<<(ACC_TOTAL + 255)/256, 256>>>();
    k_csn <<<(NP + 255)/256, 256>>>(x);
    k_mma <<<NP*8, 128>>>(tp_w0, tp_b0, tp_w, tp_b);

    k_stage0<<<NP, 256>>>(sp_w0, sp_b0, x);
    for (int s = 1; s < 4; ++s){
        const float* W = sp_w + (size_t)(s-1)*256*64;
        const float* b = sp_b + (size_t)(s-1)*64;
        k_stageN<<<128, 256>>>(s, W, b, x, fin_w, fin_b, out);
    }
}